// round 16
// baseline (speedup 1.0000x reference)
#include <cuda_runtime.h>
#include <cuda_bf16.h>
#include <cstdint>

#define N_ROWS 8192
#define D_IN   768
#define D_HID  16384
#define TOPK   32
#define TOPC   48
#define CMAX   160
#define THRESH_SIGMA 2.60f

// ---------------- scratch (static device globals: allocation-free) ----------
__device__ float          g_Wt[(size_t)D_HID * D_IN];     // W_dec^T, 48 MB
__device__ __nv_bfloat16  g_xb[(size_t)N_ROWS * D_IN];    // x in bf16
__device__ __nv_bfloat16  g_wb[(size_t)D_HID * D_IN];     // W_enc in bf16
__device__ __nv_bfloat16  g_sb[(size_t)N_ROWS * D_HID];   // bf16 screen scores, 268MB
__device__ int            g_cidx[(size_t)N_ROWS * CMAX];  // candidate columns
__device__ int            g_ccnt[N_ROWS];                 // candidate counts

// ======================= helpers ============================================
__device__ __forceinline__ uint32_t smem_u32(const void* p) {
    uint32_t a;
    asm("{ .reg .u64 t; cvta.to.shared.u64 t, %1; cvt.u32.u64 %0, t; }" : "=r"(a) : "l"(p));
    return a;
}
__device__ __forceinline__ void cp16(uint32_t saddr, const void* gaddr) {
    asm volatile("cp.async.cg.shared.global [%0], [%1], 16;\n" :: "r"(saddr), "l"(gaddr));
}
__device__ __forceinline__ void ldmatrix_x4(uint32_t& r0, uint32_t& r1, uint32_t& r2,
                                            uint32_t& r3, uint32_t addr) {
    asm volatile("ldmatrix.sync.aligned.m8n8.x4.shared.b16 {%0,%1,%2,%3}, [%4];"
                 : "=r"(r0), "=r"(r1), "=r"(r2), "=r"(r3) : "r"(addr));
}
__device__ __forceinline__ void mma_bf16(float* c, const uint32_t* a, const uint32_t* b) {
    asm volatile(
        "mma.sync.aligned.m16n8k16.row.col.f32.bf16.bf16.f32 "
        "{%0,%1,%2,%3}, {%4,%5,%6,%7}, {%8,%9}, {%0,%1,%2,%3};"
        : "+f"(c[0]), "+f"(c[1]), "+f"(c[2]), "+f"(c[3])
        : "r"(a[0]), "r"(a[1]), "r"(a[2]), "r"(a[3]), "r"(b[0]), "r"(b[1]));
}

// ------------- fused fp32 -> bf16 conversion (x then W_enc) ----------------
#define NV_X (N_ROWS * D_IN / 8)
#define NV_W (D_HID * D_IN / 8)
__global__ void convert_kernel(const float* __restrict__ xsrc,
                               const float* __restrict__ wsrc) {
    int i = blockIdx.x * blockDim.x + threadIdx.x;
    const float* src;
    __nv_bfloat16* dst;
    int j;
    if (i < NV_X) { src = xsrc; dst = g_xb; j = i; }
    else          { src = wsrc; dst = g_wb; j = i - NV_X; }
    const float4* s = reinterpret_cast<const float4*>(src) + (size_t)j * 2;
    float4 a = s[0], b = s[1];
    __nv_bfloat162 r[4];
    r[0] = __float22bfloat162_rn(make_float2(a.x, a.y));
    r[1] = __float22bfloat162_rn(make_float2(a.z, a.w));
    r[2] = __float22bfloat162_rn(make_float2(b.x, b.y));
    r[3] = __float22bfloat162_rn(make_float2(b.z, b.w));
    *reinterpret_cast<uint4*>(&dst[(size_t)j * 8]) = *reinterpret_cast<uint4*>(r);
}

// ================= bf16 HMMA screening GEMM ================================
// scores_bf16 = relu(x_bf16 @ W_enc_bf16^T)   [R6 mainloop, measured 590us]
#define GBM 128
#define GBN 128
#define GBK 64
#define NCHUNK (D_IN / GBK)        // 12
#define SMS 72                     // bf16 elems per smem row (64 + 8 pad) = 144 B
#define TILE_B (GBM * SMS * 2)     // 18432 bytes per tile buffer
#define NSTAGE 3
#define GEMM_SMEM (NSTAGE * 2 * TILE_B)   // 110592

__global__ __launch_bounds__(256, 2)
void screen_gemm_kernel(__nv_bfloat16* __restrict__ scores) {
    extern __shared__ char smem[];
    const uint32_t sbase = smem_u32(smem);
    uint32_t sA[NSTAGE], sB[NSTAGE];
    #pragma unroll
    for (int s = 0; s < NSTAGE; s++) {
        sA[s] = sbase + (uint32_t)(s * 2) * TILE_B;
        sB[s] = sbase + (uint32_t)(s * 2 + 1) * TILE_B;
    }

    const int tid = threadIdx.x, wid = tid >> 5, lane = tid & 31;
    const int bm = blockIdx.y * GBM, bn = blockIdx.x * GBN;
    const int warp_m = wid >> 2;
    const int warp_n = wid & 3;

    auto load_chunk = [&](int stage, int kc) {
        #pragma unroll
        for (int i = 0; i < 4; i++) {
            int v = tid + i * 256;
            int r = v >> 3, c = v & 7;
            uint32_t so = (uint32_t)(r * (SMS * 2) + c * 16);
            cp16(sA[stage] + so, g_xb + (size_t)(bm + r) * D_IN + kc + c * 8);
            cp16(sB[stage] + so, g_wb + (size_t)(bn + r) * D_IN + kc + c * 8);
        }
        asm volatile("cp.async.commit_group;\n" ::: "memory");
    };

    const uint32_t a_lane_off =
        (uint32_t)(((warp_m * 64) + (lane & 15)) * SMS + (lane >> 4) * 8) * 2;
    const uint32_t b_lane_off =
        (uint32_t)(((warp_n * 32) + ((lane >> 4) << 3) + (lane & 7)) * SMS
                   + ((lane >> 3) & 1) * 8) * 2;

    float acc[4][4][4];
    #pragma unroll
    for (int i = 0; i < 4; i++)
        #pragma unroll
        for (int j = 0; j < 4; j++)
            #pragma unroll
            for (int q = 0; q < 4; q++) acc[i][j][q] = 0.0f;

    load_chunk(0, 0);
    load_chunk(1, GBK);

    int cs = 0;
    for (int k = 0; k < NCHUNK; k++) {
        if (k + 1 < NCHUNK) {
            asm volatile("cp.async.wait_group 1;\n" ::: "memory");
        } else {
            asm volatile("cp.async.wait_group 0;\n" ::: "memory");
        }
        __syncthreads();

        if (k + 2 < NCHUNK) {
            int ls = cs + 2; if (ls >= NSTAGE) ls -= NSTAGE;
            load_chunk(ls, (k + 2) * GBK);
        }

        const uint32_t aB = sA[cs] + a_lane_off;
        const uint32_t bB = sB[cs] + b_lane_off;
        #pragma unroll
        for (int ks = 0; ks < 4; ks++) {
            uint32_t af[4][4], bf[2][4];
            #pragma unroll
            for (int mt = 0; mt < 4; mt++)
                ldmatrix_x4(af[mt][0], af[mt][1], af[mt][2], af[mt][3],
                            aB + (uint32_t)(mt * 16 * SMS) * 2 + (uint32_t)ks * 32);
            #pragma unroll
            for (int nt = 0; nt < 2; nt++)
                ldmatrix_x4(bf[nt][0], bf[nt][1], bf[nt][2], bf[nt][3],
                            bB + (uint32_t)(nt * 16 * SMS) * 2 + (uint32_t)ks * 32);
            #pragma unroll
            for (int mt = 0; mt < 4; mt++)
                #pragma unroll
                for (int nt = 0; nt < 4; nt++)
                    mma_bf16(acc[mt][nt], af[mt], &bf[nt >> 1][(nt & 1) * 2]);
        }

        cs = cs + 1; if (cs >= NSTAGE) cs = 0;
    }

    #pragma unroll
    for (int mt = 0; mt < 4; mt++) {
        int r0 = bm + warp_m * 64 + mt * 16 + (lane >> 2);
        #pragma unroll
        for (int nt = 0; nt < 4; nt++) {
            int col = bn + warp_n * 32 + nt * 8 + (lane & 3) * 2;
            __nv_bfloat162 lo = __float22bfloat162_rn(
                make_float2(fmaxf(acc[mt][nt][0], 0.0f), fmaxf(acc[mt][nt][1], 0.0f)));
            __nv_bfloat162 hi = __float22bfloat162_rn(
                make_float2(fmaxf(acc[mt][nt][2], 0.0f), fmaxf(acc[mt][nt][3], 0.0f)));
            *reinterpret_cast<__nv_bfloat162*>(scores + (size_t)r0 * D_HID + col)       = lo;
            *reinterpret_cast<__nv_bfloat162*>(scores + (size_t)(r0 + 8) * D_HID + col) = hi;
        }
    }
}

// ============ candidate selection: analytic threshold + rare fallback =======
// (R13 kernel verbatim: score read + latent zeroing combined — the write
//  stream fills bandwidth the latency-limited read phase leaves idle.)
__global__ __launch_bounds__(512)
void candidate_kernel(const float* __restrict__ x, float* __restrict__ latent) {
    const int row = blockIdx.x;
    const int tid = threadIdx.x, wid = tid >> 5, lid = tid & 31;
    const unsigned short* sp =
        reinterpret_cast<const unsigned short*>(g_sb + (size_t)row * D_HID);

    unsigned short v[32];
    #pragma unroll
    for (int i = 0; i < 4; i++) {
        uint4 q = *reinterpret_cast<const uint4*>(sp + tid * 8 + i * 4096);
        unsigned p;
        p = q.x; v[i*8+0] = (unsigned short)(p & 0xFFFF); v[i*8+1] = (unsigned short)(p >> 16);
        p = q.y; v[i*8+2] = (unsigned short)(p & 0xFFFF); v[i*8+3] = (unsigned short)(p >> 16);
        p = q.z; v[i*8+4] = (unsigned short)(p & 0xFFFF); v[i*8+5] = (unsigned short)(p >> 16);
        p = q.w; v[i*8+6] = (unsigned short)(p & 0xFFFF); v[i*8+7] = (unsigned short)(p >> 16);
    }

    // fire-and-forget: zero the latent row (drains under the work below)
    {
        float4 z = make_float4(0.0f, 0.0f, 0.0f, 0.0f);
        float* lp = latent + (size_t)row * D_HID;
        #pragma unroll
        for (int i = 0; i < 8; i++)
            *reinterpret_cast<float4*>(lp + tid * 4 + i * 2048) = z;
    }

    __shared__ float s_red[16];
    __shared__ int   s_tb, s_cnt, s_eq, s_slot;

    // row norm: ||x_row||^2 via block reduce (384 threads x float2)
    float sq = 0.0f;
    if (tid < D_IN / 2) {
        float2 xv = reinterpret_cast<const float2*>(x + (size_t)row * D_IN)[tid];
        sq = xv.x * xv.x + xv.y * xv.y;
    }
    #pragma unroll
    for (int o = 16; o > 0; o >>= 1) sq += __shfl_down_sync(0xffffffffu, sq, o);
    if (lid == 0) s_red[wid] = sq;
    __syncthreads();
    if (tid == 0) {
        float t2 = 0.0f;
        #pragma unroll
        for (int i = 0; i < 16; i++) t2 += s_red[i];
        float t = THRESH_SIGMA * sqrtf(t2 / (float)D_IN);
        __nv_bfloat16 tb = __float2bfloat16_rn(t);
        s_tb = (int)*reinterpret_cast<unsigned short*>(&tb);
        s_cnt = 0;
    }
    __syncthreads();
    unsigned tb = (unsigned)s_tb;

    // single count pass at the analytic threshold
    {
        int c = 0;
        #pragma unroll
        for (int i = 0; i < 32; i++) c += ((unsigned)v[i] > tb) ? 1 : 0;
        #pragma unroll
        for (int o = 16; o > 0; o >>= 1) c += __shfl_down_sync(0xffffffffu, c, o);
        if (lid == 0 && c) atomicAdd(&s_cnt, c);
    }
    __syncthreads();
    int total = s_cnt;
    __syncthreads();

    unsigned thresh;
    int mode, need_eq = 0;
    if (total >= TOPC && total <= CMAX) {
        thresh = tb;                      // fast path: strict-greater selection
        mode = 0;
    } else {
        // fallback: early-exit bisection, window [48, 96]
        mode = -1; thresh = 0u;
        unsigned lo = 0u, hi = 0x10000u;
        while (lo < hi) {
            unsigned mid = (lo + hi) >> 1;
            if (tid == 0) s_cnt = 0;
            __syncthreads();
            int c = 0;
            #pragma unroll
            for (int i = 0; i < 32; i++) c += ((unsigned)v[i] > mid) ? 1 : 0;
            #pragma unroll
            for (int o = 16; o > 0; o >>= 1) c += __shfl_down_sync(0xffffffffu, c, o);
            if (lid == 0 && c) atomicAdd(&s_cnt, c);
            __syncthreads();
            int tot = s_cnt;
            __syncthreads();
            if (tot >= 48 && tot <= 96) { thresh = mid; mode = 0; break; }
            if (tot >= 48) lo = mid + 1; else hi = mid;
        }
        if (mode < 0) {                   // converged exactly, lo == hi
            thresh = lo;
            if (tid == 0) s_cnt = 0;
            __syncthreads();
            int cg = 0, ce = 0;
            #pragma unroll
            for (int i = 0; i < 32; i++) {
                cg += ((unsigned)v[i] > thresh) ? 1 : 0;
                ce += ((unsigned)v[i] == thresh) ? 1 : 0;
            }
            int both = (cg << 16) | ce;
            #pragma unroll
            for (int o = 16; o > 0; o >>= 1) both += __shfl_down_sync(0xffffffffu, both, o);
            if (lid == 0 && both) atomicAdd(&s_cnt, both);
            __syncthreads();
            int tg = s_cnt >> 16, te = s_cnt & 0xFFFF;
            __syncthreads();
            if (tg + te <= CMAX) mode = 1;            // take all equals too
            else { mode = 2; need_eq = 48 - tg; }     // pathological eq-fill
        }
    }

    if (tid == 0) { s_eq = 0; s_slot = 0; }
    __syncthreads();

    #pragma unroll
    for (int i = 0; i < 4; i++) {
        #pragma unroll
        for (int j = 0; j < 8; j++) {
            unsigned b = (unsigned)v[i * 8 + j];
            bool sel = (b > thresh);
            if (!sel && b == thresh && mode != 0) {
                if (mode == 1) sel = true;
                else { int p = atomicAdd(&s_eq, 1); sel = (p < need_eq); }
            }
            if (sel) {
                int slot = atomicAdd(&s_slot, 1);
                g_cidx[(size_t)row * CMAX + slot] = tid * 8 + i * 4096 + j;
            }
        }
    }

    __syncthreads();
    if (tid == 0) g_ccnt[row] = s_slot;
}

// ===== exact fp32 rescore + exact top-K + fused sparse decode ==============
__global__ __launch_bounds__(512)
void rescore_decode_kernel(const float* __restrict__ x,
                           const float* __restrict__ Wenc,
                           float* __restrict__ latent,
                           float* __restrict__ recon) {
    const int row = blockIdx.x;
    const int tid = threadIdx.x, wid = tid >> 5, lid = tid & 31;
    const int C = g_ccnt[row];
    __shared__ float s_val[CMAX];
    __shared__ int   s_col[CMAX];
    __shared__ float s_tv[TOPK];
    __shared__ int   s_tc[TOPK];
    if (tid < C) s_col[tid] = g_cidx[(size_t)row * CMAX + tid];
    __syncthreads();

    const float* xr = x + (size_t)row * D_IN;
    for (int j = wid; j < C; j += 16) {
        const float* wr = Wenc + (size_t)s_col[j] * D_IN;
        float s = 0.0f, comp = 0.0f;                 // Kahan per lane
        #pragma unroll
        for (int k = lid; k < D_IN; k += 32) {
            float p = __fmul_rn(xr[k], wr[k]);
            float y = __fsub_rn(p, comp);
            float t = __fadd_rn(s, y);
            comp = __fsub_rn(__fsub_rn(t, s), y);
            s = t;
        }
        #pragma unroll
        for (int o = 16; o > 0; o >>= 1)
            s = __fadd_rn(s, __shfl_down_sync(0xffffffffu, s, o));
        if (lid == 0) s_val[j] = fmaxf(s, 0.0f);     // ReLU
    }
    __syncthreads();

    if (tid < C) {
        float vv = s_val[tid];
        int   c  = s_col[tid];
        int rank = 0;
        #pragma unroll 1
        for (int j = 0; j < C; j++) {
            float vj = s_val[j];
            rank += ((vj > vv) || (vj == vv && s_col[j] < c)) ? 1 : 0;
        }
        if (rank < TOPK) {
            latent[(size_t)row * D_HID + c] = vv;
            s_tv[rank] = vv;
            s_tc[rank] = c;
        }
    }
    __syncthreads();

    // fused decode: recon[row] = sum_j tv[j] * Wt[tc[j], :]
    float a0 = 0.0f, a1 = 0.0f;
    #pragma unroll
    for (int j = 0; j < TOPK; j++) {
        const float* wr = g_Wt + (size_t)s_tc[j] * D_IN;
        float s = s_tv[j];
        a0 = fmaf(s, wr[tid], a0);
        if (tid < D_IN - 512) a1 = fmaf(s, wr[tid + 512], a1);
    }
    recon[(size_t)row * D_IN + tid] = a0;
    if (tid < D_IN - 512) recon[(size_t)row * D_IN + 512 + tid] = a1;
}

// ---------------- W_dec transpose: [D_IN, D_HID] -> [D_HID, D_IN] -----------
__global__ void transpose_kernel(const float* __restrict__ Wdec) {
    __shared__ float tile[32][33];
    const int h0 = blockIdx.x * 32;
    const int d0 = blockIdx.y * 32;
    const int x = threadIdx.x, y = threadIdx.y;
    #pragma unroll
    for (int i = 0; i < 32; i += 8)
        tile[y + i][x] = Wdec[(size_t)(d0 + y + i) * D_HID + h0 + x];
    __syncthreads();
    #pragma unroll
    for (int i = 0; i < 32; i += 8)
        g_Wt[(size_t)(h0 + y + i) * D_IN + d0 + x] = tile[x][y + i];
}

// ---------------- launch -----------------------------------------------------
extern "C" void kernel_launch(void* const* d_in, const int* in_sizes, int n_in,
                              void* d_out, int out_size) {
    const float* x    = (const float*)d_in[0];   // [8192, 768]
    const float* Wenc = (const float*)d_in[1];   // [16384, 768]
    const float* Wdec = (const float*)d_in[2];   // [768, 16384]

    float* out    = (float*)d_out;
    float* latent = out;                                  // [8192, 16384]
    float* recon  = out + (size_t)N_ROWS * D_HID;         // [8192, 768]

    cudaFuncSetAttribute(screen_gemm_kernel,
                         cudaFuncAttributeMaxDynamicSharedMemorySize, GEMM_SMEM);

    __nv_bfloat16* sbp = nullptr;
    cudaGetSymbolAddress((void**)&sbp, g_sb);

    transpose_kernel<<<dim3(D_HID / 32, D_IN / 32), dim3(32, 8)>>>(Wdec);
    convert_kernel<<<(NV_X + NV_W) / 256, 256>>>(x, Wenc);
    screen_gemm_kernel<<<dim3(D_HID / GBN, N_ROWS / GBM), 256, GEMM_SMEM>>>(sbp);
    candidate_kernel<<<N_ROWS, 512>>>(x, latent);
    rescore_decode_kernel<<<N_ROWS, 512>>>(x, Wenc, latent, recon);
}

// round 17
// speedup vs baseline: 1.0991x; 1.0991x over previous
#include <cuda_runtime.h>
#include <cuda_bf16.h>
#include <cstdint>

#define N_ROWS 8192
#define D_IN   768
#define D_HID  16384
#define TOPK   32
#define TOPC   48
#define CMAX   160
#define THRESH_SIGMA 2.60f

// ---------------- scratch (static device globals: allocation-free) ----------
__device__ float          g_Wt[(size_t)D_HID * D_IN];     // W_dec^T, 48 MB
__device__ __nv_bfloat16  g_xb[(size_t)N_ROWS * D_IN];    // x in bf16
__device__ __nv_bfloat16  g_wb[(size_t)D_HID * D_IN];     // W_enc in bf16
__device__ __nv_bfloat16  g_sb[(size_t)N_ROWS * D_HID];   // bf16 screen scores, 268MB
__device__ int            g_cidx[(size_t)N_ROWS * CMAX];  // candidate columns
__device__ int            g_ccnt[N_ROWS];                 // candidate counts
__device__ float          g_vals[N_ROWS * TOPK];          // final top-k values (rank order)
__device__ int            g_idx [N_ROWS * TOPK];          // final top-k columns (rank order)

// ======================= helpers ============================================
__device__ __forceinline__ uint32_t smem_u32(const void* p) {
    uint32_t a;
    asm("{ .reg .u64 t; cvta.to.shared.u64 t, %1; cvt.u32.u64 %0, t; }" : "=r"(a) : "l"(p));
    return a;
}
__device__ __forceinline__ void cp16(uint32_t saddr, const void* gaddr) {
    asm volatile("cp.async.cg.shared.global [%0], [%1], 16;\n" :: "r"(saddr), "l"(gaddr));
}
__device__ __forceinline__ void ldmatrix_x4(uint32_t& r0, uint32_t& r1, uint32_t& r2,
                                            uint32_t& r3, uint32_t addr) {
    asm volatile("ldmatrix.sync.aligned.m8n8.x4.shared.b16 {%0,%1,%2,%3}, [%4];"
                 : "=r"(r0), "=r"(r1), "=r"(r2), "=r"(r3) : "r"(addr));
}
__device__ __forceinline__ void mma_bf16(float* c, const uint32_t* a, const uint32_t* b) {
    asm volatile(
        "mma.sync.aligned.m16n8k16.row.col.f32.bf16.bf16.f32 "
        "{%0,%1,%2,%3}, {%4,%5,%6,%7}, {%8,%9}, {%0,%1,%2,%3};"
        : "+f"(c[0]), "+f"(c[1]), "+f"(c[2]), "+f"(c[3])
        : "r"(a[0]), "r"(a[1]), "r"(a[2]), "r"(a[3]), "r"(b[0]), "r"(b[1]));
}

// ------------- fused fp32 -> bf16 conversion (x then W_enc) ----------------
#define NV_X (N_ROWS * D_IN / 8)
#define NV_W (D_HID * D_IN / 8)
__global__ void convert_kernel(const float* __restrict__ xsrc,
                               const float* __restrict__ wsrc) {
    int i = blockIdx.x * blockDim.x + threadIdx.x;
    const float* src;
    __nv_bfloat16* dst;
    int j;
    if (i < NV_X) { src = xsrc; dst = g_xb; j = i; }
    else          { src = wsrc; dst = g_wb; j = i - NV_X; }
    const float4* s = reinterpret_cast<const float4*>(src) + (size_t)j * 2;
    float4 a = s[0], b = s[1];
    __nv_bfloat162 r[4];
    r[0] = __float22bfloat162_rn(make_float2(a.x, a.y));
    r[1] = __float22bfloat162_rn(make_float2(a.z, a.w));
    r[2] = __float22bfloat162_rn(make_float2(b.x, b.y));
    r[3] = __float22bfloat162_rn(make_float2(b.z, b.w));
    *reinterpret_cast<uint4*>(&dst[(size_t)j * 8]) = *reinterpret_cast<uint4*>(r);
}

// ================= bf16 HMMA screening GEMM ================================
// scores_bf16 = relu(x_bf16 @ W_enc_bf16^T)   [R6 mainloop, measured 590us]
#define GBM 128
#define GBN 128
#define GBK 64
#define NCHUNK (D_IN / GBK)        // 12
#define SMS 72                     // bf16 elems per smem row (64 + 8 pad) = 144 B
#define TILE_B (GBM * SMS * 2)     // 18432 bytes per tile buffer
#define NSTAGE 3
#define GEMM_SMEM (NSTAGE * 2 * TILE_B)   // 110592

__global__ __launch_bounds__(256, 2)
void screen_gemm_kernel(__nv_bfloat16* __restrict__ scores) {
    extern __shared__ char smem[];
    const uint32_t sbase = smem_u32(smem);
    uint32_t sA[NSTAGE], sB[NSTAGE];
    #pragma unroll
    for (int s = 0; s < NSTAGE; s++) {
        sA[s] = sbase + (uint32_t)(s * 2) * TILE_B;
        sB[s] = sbase + (uint32_t)(s * 2 + 1) * TILE_B;
    }

    const int tid = threadIdx.x, wid = tid >> 5, lane = tid & 31;
    const int bm = blockIdx.y * GBM, bn = blockIdx.x * GBN;
    const int warp_m = wid >> 2;
    const int warp_n = wid & 3;

    auto load_chunk = [&](int stage, int kc) {
        #pragma unroll
        for (int i = 0; i < 4; i++) {
            int v = tid + i * 256;
            int r = v >> 3, c = v & 7;
            uint32_t so = (uint32_t)(r * (SMS * 2) + c * 16);
            cp16(sA[stage] + so, g_xb + (size_t)(bm + r) * D_IN + kc + c * 8);
            cp16(sB[stage] + so, g_wb + (size_t)(bn + r) * D_IN + kc + c * 8);
        }
        asm volatile("cp.async.commit_group;\n" ::: "memory");
    };

    const uint32_t a_lane_off =
        (uint32_t)(((warp_m * 64) + (lane & 15)) * SMS + (lane >> 4) * 8) * 2;
    const uint32_t b_lane_off =
        (uint32_t)(((warp_n * 32) + ((lane >> 4) << 3) + (lane & 7)) * SMS
                   + ((lane >> 3) & 1) * 8) * 2;

    float acc[4][4][4];
    #pragma unroll
    for (int i = 0; i < 4; i++)
        #pragma unroll
        for (int j = 0; j < 4; j++)
            #pragma unroll
            for (int q = 0; q < 4; q++) acc[i][j][q] = 0.0f;

    load_chunk(0, 0);
    load_chunk(1, GBK);

    int cs = 0;
    for (int k = 0; k < NCHUNK; k++) {
        if (k + 1 < NCHUNK) {
            asm volatile("cp.async.wait_group 1;\n" ::: "memory");
        } else {
            asm volatile("cp.async.wait_group 0;\n" ::: "memory");
        }
        __syncthreads();

        if (k + 2 < NCHUNK) {
            int ls = cs + 2; if (ls >= NSTAGE) ls -= NSTAGE;
            load_chunk(ls, (k + 2) * GBK);
        }

        const uint32_t aB = sA[cs] + a_lane_off;
        const uint32_t bB = sB[cs] + b_lane_off;
        #pragma unroll
        for (int ks = 0; ks < 4; ks++) {
            uint32_t af[4][4], bf[2][4];
            #pragma unroll
            for (int mt = 0; mt < 4; mt++)
                ldmatrix_x4(af[mt][0], af[mt][1], af[mt][2], af[mt][3],
                            aB + (uint32_t)(mt * 16 * SMS) * 2 + (uint32_t)ks * 32);
            #pragma unroll
            for (int nt = 0; nt < 2; nt++)
                ldmatrix_x4(bf[nt][0], bf[nt][1], bf[nt][2], bf[nt][3],
                            bB + (uint32_t)(nt * 16 * SMS) * 2 + (uint32_t)ks * 32);
            #pragma unroll
            for (int mt = 0; mt < 4; mt++)
                #pragma unroll
                for (int nt = 0; nt < 4; nt++)
                    mma_bf16(acc[mt][nt], af[mt], &bf[nt >> 1][(nt & 1) * 2]);
        }

        cs = cs + 1; if (cs >= NSTAGE) cs = 0;
    }

    #pragma unroll
    for (int mt = 0; mt < 4; mt++) {
        int r0 = bm + warp_m * 64 + mt * 16 + (lane >> 2);
        #pragma unroll
        for (int nt = 0; nt < 4; nt++) {
            int col = bn + warp_n * 32 + nt * 8 + (lane & 3) * 2;
            __nv_bfloat162 lo = __float22bfloat162_rn(
                make_float2(fmaxf(acc[mt][nt][0], 0.0f), fmaxf(acc[mt][nt][1], 0.0f)));
            __nv_bfloat162 hi = __float22bfloat162_rn(
                make_float2(fmaxf(acc[mt][nt][2], 0.0f), fmaxf(acc[mt][nt][3], 0.0f)));
            *reinterpret_cast<__nv_bfloat162*>(scores + (size_t)r0 * D_HID + col)       = lo;
            *reinterpret_cast<__nv_bfloat162*>(scores + (size_t)(r0 + 8) * D_HID + col) = hi;
        }
    }
}

// ============ candidate selection: analytic threshold + rare fallback =======
// (R13 kernel verbatim: score read + latent zeroing combined — the write
//  stream fills bandwidth the latency-limited read phase leaves idle.)
__global__ __launch_bounds__(512)
void candidate_kernel(const float* __restrict__ x, float* __restrict__ latent) {
    const int row = blockIdx.x;
    const int tid = threadIdx.x, wid = tid >> 5, lid = tid & 31;
    const unsigned short* sp =
        reinterpret_cast<const unsigned short*>(g_sb + (size_t)row * D_HID);

    unsigned short v[32];
    #pragma unroll
    for (int i = 0; i < 4; i++) {
        uint4 q = *reinterpret_cast<const uint4*>(sp + tid * 8 + i * 4096);
        unsigned p;
        p = q.x; v[i*8+0] = (unsigned short)(p & 0xFFFF); v[i*8+1] = (unsigned short)(p >> 16);
        p = q.y; v[i*8+2] = (unsigned short)(p & 0xFFFF); v[i*8+3] = (unsigned short)(p >> 16);
        p = q.z; v[i*8+4] = (unsigned short)(p & 0xFFFF); v[i*8+5] = (unsigned short)(p >> 16);
        p = q.w; v[i*8+6] = (unsigned short)(p & 0xFFFF); v[i*8+7] = (unsigned short)(p >> 16);
    }

    // fire-and-forget: zero the latent row (drains under the work below)
    {
        float4 z = make_float4(0.0f, 0.0f, 0.0f, 0.0f);
        float* lp = latent + (size_t)row * D_HID;
        #pragma unroll
        for (int i = 0; i < 8; i++)
            *reinterpret_cast<float4*>(lp + tid * 4 + i * 2048) = z;
    }

    __shared__ float s_red[16];
    __shared__ int   s_tb, s_cnt, s_eq, s_slot;

    // row norm: ||x_row||^2 via block reduce (384 threads x float2)
    float sq = 0.0f;
    if (tid < D_IN / 2) {
        float2 xv = reinterpret_cast<const float2*>(x + (size_t)row * D_IN)[tid];
        sq = xv.x * xv.x + xv.y * xv.y;
    }
    #pragma unroll
    for (int o = 16; o > 0; o >>= 1) sq += __shfl_down_sync(0xffffffffu, sq, o);
    if (lid == 0) s_red[wid] = sq;
    __syncthreads();
    if (tid == 0) {
        float t2 = 0.0f;
        #pragma unroll
        for (int i = 0; i < 16; i++) t2 += s_red[i];
        float t = THRESH_SIGMA * sqrtf(t2 / (float)D_IN);
        __nv_bfloat16 tb = __float2bfloat16_rn(t);
        s_tb = (int)*reinterpret_cast<unsigned short*>(&tb);
        s_cnt = 0;
    }
    __syncthreads();
    unsigned tb = (unsigned)s_tb;

    // single count pass at the analytic threshold
    {
        int c = 0;
        #pragma unroll
        for (int i = 0; i < 32; i++) c += ((unsigned)v[i] > tb) ? 1 : 0;
        #pragma unroll
        for (int o = 16; o > 0; o >>= 1) c += __shfl_down_sync(0xffffffffu, c, o);
        if (lid == 0 && c) atomicAdd(&s_cnt, c);
    }
    __syncthreads();
    int total = s_cnt;
    __syncthreads();

    unsigned thresh;
    int mode, need_eq = 0;
    if (total >= TOPC && total <= CMAX) {
        thresh = tb;                      // fast path: strict-greater selection
        mode = 0;
    } else {
        // fallback: early-exit bisection, window [48, 96]
        mode = -1; thresh = 0u;
        unsigned lo = 0u, hi = 0x10000u;
        while (lo < hi) {
            unsigned mid = (lo + hi) >> 1;
            if (tid == 0) s_cnt = 0;
            __syncthreads();
            int c = 0;
            #pragma unroll
            for (int i = 0; i < 32; i++) c += ((unsigned)v[i] > mid) ? 1 : 0;
            #pragma unroll
            for (int o = 16; o > 0; o >>= 1) c += __shfl_down_sync(0xffffffffu, c, o);
            if (lid == 0 && c) atomicAdd(&s_cnt, c);
            __syncthreads();
            int tot = s_cnt;
            __syncthreads();
            if (tot >= 48 && tot <= 96) { thresh = mid; mode = 0; break; }
            if (tot >= 48) lo = mid + 1; else hi = mid;
        }
        if (mode < 0) {                   // converged exactly, lo == hi
            thresh = lo;
            if (tid == 0) s_cnt = 0;
            __syncthreads();
            int cg = 0, ce = 0;
            #pragma unroll
            for (int i = 0; i < 32; i++) {
                cg += ((unsigned)v[i] > thresh) ? 1 : 0;
                ce += ((unsigned)v[i] == thresh) ? 1 : 0;
            }
            int both = (cg << 16) | ce;
            #pragma unroll
            for (int o = 16; o > 0; o >>= 1) both += __shfl_down_sync(0xffffffffu, both, o);
            if (lid == 0 && both) atomicAdd(&s_cnt, both);
            __syncthreads();
            int tg = s_cnt >> 16, te = s_cnt & 0xFFFF;
            __syncthreads();
            if (tg + te <= CMAX) mode = 1;            // take all equals too
            else { mode = 2; need_eq = 48 - tg; }     // pathological eq-fill
        }
    }

    if (tid == 0) { s_eq = 0; s_slot = 0; }
    __syncthreads();

    #pragma unroll
    for (int i = 0; i < 4; i++) {
        #pragma unroll
        for (int j = 0; j < 8; j++) {
            unsigned b = (unsigned)v[i * 8 + j];
            bool sel = (b > thresh);
            if (!sel && b == thresh && mode != 0) {
                if (mode == 1) sel = true;
                else { int p = atomicAdd(&s_eq, 1); sel = (p < need_eq); }
            }
            if (sel) {
                int slot = atomicAdd(&s_slot, 1);
                g_cidx[(size_t)row * CMAX + slot] = tid * 8 + i * 4096 + j;
            }
        }
    }

    __syncthreads();
    if (tid == 0) g_ccnt[row] = s_slot;
}

// ============ exact fp32 rescore of candidates + exact top-K ================
// Plain fp32 FMA chain (no Kahan): 4x shorter dependency chain; x row staged
// in shared memory once per block instead of 16 per-warp L2 re-reads.
__global__ __launch_bounds__(512)
void rescore_kernel(const float* __restrict__ x, const float* __restrict__ Wenc,
                    float* __restrict__ latent) {
    const int row = blockIdx.x;
    const int tid = threadIdx.x, wid = tid >> 5, lid = tid & 31;
    const int C = g_ccnt[row];
    __shared__ float s_x[D_IN];
    __shared__ float s_val[CMAX];
    __shared__ int   s_col[CMAX];
    if (tid < C) s_col[tid] = g_cidx[(size_t)row * CMAX + tid];
    if (tid < D_IN / 2) {
        float2 xv = reinterpret_cast<const float2*>(x + (size_t)row * D_IN)[tid];
        s_x[tid * 2]     = xv.x;
        s_x[tid * 2 + 1] = xv.y;
    }
    __syncthreads();

    for (int j = wid; j < C; j += 16) {
        const float* wr = Wenc + (size_t)s_col[j] * D_IN;
        float s = 0.0f;
        #pragma unroll
        for (int k = lid; k < D_IN; k += 32)
            s = __fmaf_rn(s_x[k], wr[k], s);
        #pragma unroll
        for (int o = 16; o > 0; o >>= 1)
            s = __fadd_rn(s, __shfl_down_sync(0xffffffffu, s, o));
        if (lid == 0) s_val[j] = fmaxf(s, 0.0f);     // ReLU
    }
    __syncthreads();

    if (tid < C) {
        float vv = s_val[tid];
        int   c  = s_col[tid];
        int rank = 0;
        #pragma unroll 1
        for (int j = 0; j < C; j++) {
            float vj = s_val[j];
            rank += ((vj > vv) || (vj == vv && s_col[j] < c)) ? 1 : 0;
        }
        if (rank < TOPK) {
            latent[(size_t)row * D_HID + c] = vv;
            g_vals[row * TOPK + rank] = vv;
            g_idx [row * TOPK + rank] = c;
        }
    }
}

// ---------------- W_dec transpose: [D_IN, D_HID] -> [D_HID, D_IN] -----------
__global__ void transpose_kernel(const float* __restrict__ Wdec) {
    __shared__ float tile[32][33];
    const int h0 = blockIdx.x * 32;
    const int d0 = blockIdx.y * 32;
    const int x = threadIdx.x, y = threadIdx.y;
    #pragma unroll
    for (int i = 0; i < 32; i += 8)
        tile[y + i][x] = Wdec[(size_t)(d0 + y + i) * D_HID + h0 + x];
    __syncthreads();
    #pragma unroll
    for (int i = 0; i < 32; i += 8)
        g_Wt[(size_t)(h0 + y + i) * D_IN + d0 + x] = tile[x][y + i];
}

// ---------------- sparse decoder: recon = latent_sparse @ W_dec^T -----------
__global__ __launch_bounds__(256)
void decode_kernel(float* __restrict__ recon) {
    const int row = blockIdx.x;
    const int tid = threadIdx.x;
    __shared__ float sv[TOPK];
    __shared__ int   si[TOPK];
    if (tid < TOPK) {
        sv[tid] = g_vals[row * TOPK + tid];
        si[tid] = g_idx [row * TOPK + tid];
    }
    __syncthreads();

    float a0 = 0.0f, a1 = 0.0f, a2 = 0.0f;
    #pragma unroll
    for (int j = 0; j < TOPK; j++) {
        const float* wr = g_Wt + (size_t)si[j] * D_IN;
        float s = sv[j];
        a0 = fmaf(s, wr[tid],       a0);
        a1 = fmaf(s, wr[tid + 256], a1);
        a2 = fmaf(s, wr[tid + 512], a2);
    }
    size_t off = (size_t)row * D_IN + tid;
    recon[off]       = a0;
    recon[off + 256] = a1;
    recon[off + 512] = a2;
}

// ---------------- launch -----------------------------------------------------
extern "C" void kernel_launch(void* const* d_in, const int* in_sizes, int n_in,
                              void* d_out, int out_size) {
    const float* x    = (const float*)d_in[0];   // [8192, 768]
    const float* Wenc = (const float*)d_in[1];   // [16384, 768]
    const float* Wdec = (const float*)d_in[2];   // [768, 16384]

    float* out    = (float*)d_out;
    float* latent = out;                                  // [8192, 16384]
    float* recon  = out + (size_t)N_ROWS * D_HID;         // [8192, 768]

    cudaFuncSetAttribute(screen_gemm_kernel,
                         cudaFuncAttributeMaxDynamicSharedMemorySize, GEMM_SMEM);

    __nv_bfloat16* sbp = nullptr;
    cudaGetSymbolAddress((void**)&sbp, g_sb);

    transpose_kernel<<<dim3(D_HID / 32, D_IN / 32), dim3(32, 8)>>>(Wdec);
    convert_kernel<<<(NV_X + NV_W) / 256, 256>>>(x, Wenc);
    screen_gemm_kernel<<<dim3(D_HID / GBN, N_ROWS / GBM), 256, GEMM_SMEM>>>(sbp);
    candidate_kernel<<<N_ROWS, 512>>>(x, latent);
    rescore_kernel<<<N_ROWS, 512>>>(x, Wenc, latent);
    decode_kernel<<<N_ROWS, 256>>>(recon);
}